// round 14
// baseline (speedup 1.0000x reference)
#include <cuda_runtime.h>
#include <cuda_bf16.h>
#include <cstdint>

#define T_TOK 8192
#define DIM   1024
#define NE    8
#define NP    (T_TOK * 2)      // 16384 (token,expert) pairs

#define TM    128
#define TN    128
#define TK    32               // bf16 K per pipeline stage
#define NCH   (DIM / TK)       // 32 chunks
#define NSTG  3
#define MAXTILES 24

// stage layout: Ah(8K) Al(8K) Bh(8K) Bl(8K) = 32KB
#define STG_BYTES 32768u
#define SM_STG0 1024u
#define SM_TOTAL (1024 + NSTG * 32768)

// ---------------- static device scratch (allocation-free) --------------------
__device__ __nv_bfloat16 g_Xh[(size_t)NP * DIM], g_Xl[(size_t)NP * DIM];
__device__ __nv_bfloat16 g_Hh[(size_t)NP * DIM], g_Hl[(size_t)NP * DIM];
__device__ __nv_bfloat16 g_W1h[(size_t)NE * DIM * DIM], g_W1l[(size_t)NE * DIM * DIM];
__device__ __nv_bfloat16 g_W2h[(size_t)NE * DIM * DIM], g_W2l[(size_t)NE * DIM * DIM];
__device__ float g_Y[(size_t)NP * DIM];
__device__ int g_perm_src[NP];
__device__ int g_counts[NE], g_offsets[NE];

// ---------------- PTX helpers ------------------------------------------------
__device__ __forceinline__ uint32_t smem_u32(const void* p) {
    uint32_t a;
    asm("{ .reg .u64 t; cvta.to.shared.u64 t, %1; cvt.u32.u64 %0, t; }" : "=r"(a) : "l"(p));
    return a;
}
__device__ __forceinline__ void cpa16(uint32_t dst, const void* src) {
    asm volatile("cp.async.cg.shared.global [%0], [%1], 16;" :: "r"(dst), "l"(src));
}
#define CP_COMMIT() asm volatile("cp.async.commit_group;" ::: "memory")
#define CP_WAIT(n)  asm volatile("cp.async.wait_group %0;" :: "n"(n) : "memory")

__device__ __forceinline__ void ldsm4(uint32_t& r0, uint32_t& r1, uint32_t& r2,
                                      uint32_t& r3, uint32_t addr) {
    asm volatile("ldmatrix.sync.aligned.m8n8.x4.shared.b16 {%0,%1,%2,%3}, [%4];"
                 : "=r"(r0), "=r"(r1), "=r"(r2), "=r"(r3) : "r"(addr));
}
__device__ __forceinline__ void mma16816(float* c, const uint32_t* a,
                                         uint32_t b0, uint32_t b1) {
    asm volatile("mma.sync.aligned.m16n8k16.row.col.f32.bf16.bf16.f32 "
                 "{%0,%1,%2,%3}, {%4,%5,%6,%7}, {%8,%9}, {%0,%1,%2,%3};"
                 : "+f"(c[0]), "+f"(c[1]), "+f"(c[2]), "+f"(c[3])
                 : "r"(a[0]), "r"(a[1]), "r"(a[2]), "r"(a[3]), "r"(b0), "r"(b1));
}

// 16B-chunk XOR swizzle on 64B rows; conflict-free for 8-row ldmatrix groups.
__device__ __forceinline__ uint32_t sw_off(int r, int c16) {
    return (uint32_t)(r * 64 + ((c16 ^ ((r >> 1) & 3)) << 4));
}

// ---------------- fused grouping (single block) -------------------------------
__global__ void k_group(const int* __restrict__ idx) {
    __shared__ int sc[NE], scur[NE];
    const int tid = threadIdx.x;                 // 512 threads
    if (tid < NE) sc[tid] = 0;
    __syncthreads();

    int lc[NE];
    #pragma unroll
    for (int e = 0; e < NE; ++e) lc[e] = 0;
    for (int i = tid; i < NP; i += 512) lc[idx[i]]++;
    #pragma unroll
    for (int e = 0; e < NE; ++e)
        if (lc[e]) atomicAdd(&sc[e], lc[e]);
    __syncthreads();

    if (tid == 0) {
        int s = 0;
        for (int e = 0; e < NE; ++e) {
            g_counts[e]  = sc[e];
            g_offsets[e] = s;
            scur[e] = s;
            s += sc[e];
        }
    }
    __syncthreads();

    int base[NE];
    #pragma unroll
    for (int e = 0; e < NE; ++e)
        base[e] = lc[e] ? atomicAdd(&scur[e], lc[e]) : 0;

    int used[NE];
    #pragma unroll
    for (int e = 0; e < NE; ++e) used[e] = 0;
    for (int i = tid; i < NP; i += 512) {
        int e = idx[i];
        g_perm_src[base[e] + used[e]++] = i;
    }
}

// ---------------- fp32 -> bf16 hi/lo converts --------------------------------
union B8 { __nv_bfloat16 b[8]; uint4 u; };

__device__ __forceinline__ void split8(const float* v, B8& h, B8& l) {
    #pragma unroll
    for (int j = 0; j < 8; ++j) {
        __nv_bfloat16 hv = __float2bfloat16(v[j]);
        h.b[j] = hv;
        l.b[j] = __float2bfloat16(v[j] - __bfloat162float(hv));
    }
}

__global__ void k_convert_x(const float* __restrict__ x) {
    int i = blockIdx.x * blockDim.x + threadIdx.x;
    if (i >= NP * (DIM / 8)) return;
    int p  = i >> 7;
    int c8 = (i & 127) << 3;
    int tok = g_perm_src[p] >> 1;
    float v[8];
    *(float4*)&v[0] = *(const float4*)&x[(size_t)tok * DIM + c8];
    *(float4*)&v[4] = *(const float4*)&x[(size_t)tok * DIM + c8 + 4];
    B8 h, l; split8(v, h, l);
    *(uint4*)&g_Xh[(size_t)p * DIM + c8] = h.u;
    *(uint4*)&g_Xl[(size_t)p * DIM + c8] = l.u;
}

// Converts BOTH weight tensors in one launch.
__global__ void k_convert_w2(const float* __restrict__ W1,
                             const float* __restrict__ W2) {
    size_t i = (size_t)blockIdx.x * blockDim.x + threadIdx.x;
    const size_t half = (size_t)NE * DIM * DIM / 8;
    if (i >= 2 * half) return;
    const int which = (i >= half);
    const float* W = which ? W2 : W1;
    size_t b0 = (which ? (i - half) : i) * 8;
    float v[8];
    *(float4*)&v[0] = *(const float4*)&W[b0];
    *(float4*)&v[4] = *(const float4*)&W[b0 + 4];
    B8 h, l; split8(v, h, l);
    __nv_bfloat16* dh = which ? g_W2h : g_W1h;
    __nv_bfloat16* dl = which ? g_W2l : g_W1l;
    *(uint4*)&dh[b0] = h.u;
    *(uint4*)&dl[b0] = l.u;
}

// ---------------- mma.sync grouped GEMM (TM=128, TN=128, warp 64x32) ---------
// All loop-varying address math reduced to: rotating stage bases (2 regs),
// 6 precomputed ldsm swizzle offsets (s=1 = ^32), 4 advancing global pointers,
// 2 precomputed store swizzle offsets.
template <int STAGE>
__global__ __launch_bounds__(256, 2)
void k_gemm(const float* __restrict__ fw)
{
    extern __shared__ __align__(1024) char smem[];
    const int e   = blockIdx.z;
    const int cnt = g_counts[e];
    const int m0  = blockIdx.y * TM;
    if (m0 >= cnt) return;
    const int off = g_offsets[e];
    const int n0  = blockIdx.x * TN;
    const int tid = threadIdx.x;
    const int wid  = tid >> 5;
    const int lane = tid & 31;

    const uint32_t sb = smem_u32(smem);
    int* rowA = (int*)smem;
    if (tid < TM) rowA[tid] = off + min(m0 + tid, cnt - 1);
    __syncthreads();

    const __nv_bfloat16* __restrict__ Ah = (STAGE == 1) ? g_Xh : g_Hh;
    const __nv_bfloat16* __restrict__ Al = (STAGE == 1) ? g_Xl : g_Hl;
    const __nv_bfloat16* __restrict__ Bh =
        ((STAGE == 1) ? g_W1h : g_W2h) + (size_t)e * DIM * DIM;
    const __nv_bfloat16* __restrict__ Bl =
        ((STAGE == 1) ? g_W1l : g_W2l) + (size_t)e * DIM * DIM;

    const int r0l = tid >> 2, c0l = tid & 3;

    // ---- persistent load state: 4 advancing hi-pointers + lo deltas ----
    const __nv_bfloat16* pA0 = Ah + (size_t)rowA[r0l]      * DIM + c0l * 8;
    const __nv_bfloat16* pA1 = Ah + (size_t)rowA[r0l + 64] * DIM + c0l * 8;
    const __nv_bfloat16* pB0 = Bh + (size_t)(n0 + r0l)      * DIM + c0l * 8;
    const __nv_bfloat16* pB1 = Bh + (size_t)(n0 + r0l + 64) * DIM + c0l * 8;
    const ptrdiff_t dAl = Al - Ah;    // warp-uniform
    const ptrdiff_t dBl = Bl - Bh;
    const uint32_t st0 = sw_off(r0l,      c0l);   // store swizzles (region-relative)
    const uint32_t st1 = sw_off(r0l + 64, c0l);

    // regions within a stage: AH=+0, AL=+8192, BH=+16384, BL=+24576
    auto load_to = [&](uint32_t base) {
        cpa16(base +          st0, pA0);
        cpa16(base +  8192u + st0, pA0 + dAl);
        cpa16(base + 16384u + st0, pB0);
        cpa16(base + 24576u + st0, pB0 + dBl);
        cpa16(base +          st1, pA1);
        cpa16(base +  8192u + st1, pA1 + dAl);
        cpa16(base + 16384u + st1, pB1);
        cpa16(base + 24576u + st1, pB1 + dBl);
        CP_COMMIT();
        pA0 += TK; pA1 += TK; pB0 += TK; pB1 += TK;
    };

    // warp tiling: wm in {0,1} (64-row band), wn in {0..3} (32-col band)
    const int wm = wid & 1, wn = wid >> 1;
    const int lrow = lane & 15;
    const int lhi  = lane >> 4;

    // ---- precomputed ldsm swizzle offsets for s=0 (csel = lhi) ----
    uint32_t pA[4], pB[2];
    #pragma unroll
    for (int mt = 0; mt < 4; ++mt)
        pA[mt] = sw_off(wm * 64 + mt * 16 + lrow, lhi);             // AH-relative
    #pragma unroll
    for (int g = 0; g < 2; ++g)
        pB[g] = 16384u + sw_off(wn * 32 + g * 16 + lrow, lhi);      // BH region

    float acc[4][4][4];
    #pragma unroll
    for (int i = 0; i < 4; ++i)
        #pragma unroll
        for (int j = 0; j < 4; ++j)
            #pragma unroll
            for (int k = 0; k < 4; ++k) acc[i][j][k] = 0.0f;

    // rotating stage bases
    const uint32_t stgLo = sb + SM_STG0;
    const uint32_t stgHi = sb + SM_STG0 + (NSTG - 1) * STG_BYTES;
    uint32_t stg  = stgLo;                       // compute stage for chunk c
    uint32_t lstg = stgLo + 2 * STG_BYTES;       // load target = (c+2)%3

    load_to(stgLo);
    load_to(stgLo + STG_BYTES);

    for (int c = 0; c < NCH; ++c) {
        CP_WAIT(NSTG - 2);
        __syncthreads();
        if (c + NSTG - 1 < NCH) {
            load_to(lstg);
            lstg = (lstg == stgHi) ? stgLo : (lstg + STG_BYTES);
        } else CP_COMMIT();

        #pragma unroll
        for (int s = 0; s < 2; ++s) {
            const uint32_t sx = s ? 32u : 0u;    // s toggles csel bit1 -> offset bit5

            // ---- load ah + bh ----
            uint32_t ah[4][4];
            #pragma unroll
            for (int mt = 0; mt < 4; ++mt)
                ldsm4(ah[mt][0], ah[mt][1], ah[mt][2], ah[mt][3],
                      stg + (pA[mt] ^ sx));
            uint32_t bh[4][2];
            #pragma unroll
            for (int g = 0; g < 2; ++g) {
                uint32_t t0, t1, t2, t3;
                ldsm4(t0, t1, t2, t3, stg + (pB[g] ^ sx));
                bh[g * 2 + 0][0] = t0; bh[g * 2 + 0][1] = t2;
                bh[g * 2 + 1][0] = t1; bh[g * 2 + 1][1] = t3;
            }
            #pragma unroll
            for (int mt = 0; mt < 4; ++mt)
                #pragma unroll
                for (int nt = 0; nt < 4; ++nt)
                    mma16816(acc[mt][nt], ah[mt], bh[nt][0], bh[nt][1]);

            // ---- t2: Al x Bh ----
            uint32_t al[4][4];
            #pragma unroll
            for (int mt = 0; mt < 4; ++mt)
                ldsm4(al[mt][0], al[mt][1], al[mt][2], al[mt][3],
                      stg + 8192u + (pA[mt] ^ sx));
            #pragma unroll
            for (int mt = 0; mt < 4; ++mt)
                #pragma unroll
                for (int nt = 0; nt < 4; ++nt)
                    mma16816(acc[mt][nt], al[mt], bh[nt][0], bh[nt][1]);

            // ---- t3: Ah x Bl ----
            uint32_t bl[4][2];
            #pragma unroll
            for (int g = 0; g < 2; ++g) {
                uint32_t t0, t1, t2, t3;
                ldsm4(t0, t1, t2, t3, stg + 8192u + (pB[g] ^ sx));
                bl[g * 2 + 0][0] = t0; bl[g * 2 + 0][1] = t2;
                bl[g * 2 + 1][0] = t1; bl[g * 2 + 1][1] = t3;
            }
            #pragma unroll
            for (int mt = 0; mt < 4; ++mt)
                #pragma unroll
                for (int nt = 0; nt < 4; ++nt)
                    mma16816(acc[mt][nt], ah[mt], bl[nt][0], bl[nt][1]);
        }
        stg = (stg == stgHi) ? stgLo : (stg + STG_BYTES);
    }

    // ---------------- epilogue (coalesced stores; STAGE2 -> g_Y) -------------
    const int lq = lane >> 2;
    const int lr = lane & 3;
    #pragma unroll
    for (int mt = 0; mt < 4; ++mt) {
        #pragma unroll
        for (int half = 0; half < 2; ++half) {
            const int m  = wm * 64 + mt * 16 + half * 8 + lq;
            const int gr = m0 + m;
            if (gr >= cnt) continue;
            const int p = off + gr;
            int   dstrow = p;
            float wt = 1.0f;
            if (STAGE == 2) {
                int src = g_perm_src[p];
                wt = fw[src];
                dstrow = src;
            }
            #pragma unroll
            for (int nt = 0; nt < 4; ++nt) {
                const int col = n0 + wn * 32 + nt * 8 + lr * 2;
                float v0 = fmaxf(acc[mt][nt][half * 2 + 0], 0.0f);
                float v1 = fmaxf(acc[mt][nt][half * 2 + 1], 0.0f);
                if (STAGE == 1) {
                    __nv_bfloat16 h0 = __float2bfloat16(v0);
                    __nv_bfloat16 h1 = __float2bfloat16(v1);
                    __nv_bfloat16 l0 = __float2bfloat16(v0 - __bfloat162float(h0));
                    __nv_bfloat16 l1 = __float2bfloat16(v1 - __bfloat162float(h1));
                    __nv_bfloat162 hp; hp.x = h0; hp.y = h1;
                    __nv_bfloat162 lp; lp.x = l0; lp.y = l1;
                    *(__nv_bfloat162*)&g_Hh[(size_t)p * DIM + col] = hp;
                    *(__nv_bfloat162*)&g_Hl[(size_t)p * DIM + col] = lp;
                } else {
                    float2 o; o.x = v0 * wt; o.y = v1 * wt;
                    *(float2*)&g_Y[(size_t)dstrow * DIM + col] = o;
                }
            }
        }
    }
}

// ---------------- combine: out[t] = Y[2t] + Y[2t+1] ---------------------------
__global__ void k_combine(float* __restrict__ out) {
    int i = blockIdx.x * blockDim.x + threadIdx.x;
    if (i >= T_TOK * DIM / 4) return;
    int t = i / (DIM / 4);
    const float4* y = (const float4*)g_Y;
    float4 a = y[(size_t)i + (size_t)t * (DIM / 4)];
    float4 b = y[(size_t)i + (size_t)t * (DIM / 4) + (DIM / 4)];
    float4 o; o.x = a.x + b.x; o.y = a.y + b.y; o.z = a.z + b.z; o.w = a.w + b.w;
    ((float4*)out)[i] = o;
}

// ---------------- launch ------------------------------------------------------
extern "C" void kernel_launch(void* const* d_in, const int* in_sizes, int n_in,
                              void* d_out, int out_size) {
    const float* x   = (const float*)d_in[0];
    const int*   fei = (const int*)d_in[1];
    const float* few = (const float*)d_in[2];
    const float* W1  = (const float*)d_in[3];
    const float* W2  = (const float*)d_in[4];
    float* out = (float*)d_out;

    cudaFuncSetAttribute(k_gemm<1>, cudaFuncAttributeMaxDynamicSharedMemorySize, SM_TOTAL);
    cudaFuncSetAttribute(k_gemm<2>, cudaFuncAttributeMaxDynamicSharedMemorySize, SM_TOTAL);

    dim3 grid(DIM / TN, MAXTILES, NE);   // 8 x 24 x 8 = 1536 CTAs

    k_group<<<1, 512>>>(fei);                                             // 1
    k_convert_x<<<(NP * (DIM / 8) + 255) / 256, 256>>>(x);                // 2
    k_convert_w2<<<(2 * NE * DIM * DIM / 8 + 255) / 256, 256>>>(W1, W2);  // 3
    k_gemm<1><<<grid, 256, SM_TOTAL>>>(few);                              // 4 <- ncu
    k_gemm<2><<<grid, 256, SM_TOTAL>>>(few);                              // 5
    k_combine<<<(T_TOK * DIM / 4 + 255) / 256, 256>>>(out);               // 6
}

// round 15
// speedup vs baseline: 1.1123x; 1.1123x over previous
#include <cuda_runtime.h>
#include <cuda_bf16.h>
#include <cstdint>

#define T_TOK 8192
#define DIM   1024
#define NE    8
#define NP    (T_TOK * 2)      // 16384 (token,expert) pairs

#define TM    128
#define TN    128
#define TK    32               // bf16 K per pipeline stage
#define NCH   (DIM / TK)       // 32 chunks
#define NSTG  3
#define MAXTILES 24

// stage layout: Ah(8K) Al(8K) Bh(8K) Bl(8K) = 32KB
#define STG_BYTES 32768u
#define SM_STG0 1024u
#define SM_TOTAL (1024 + NSTG * 32768)

// ---------------- static device scratch (allocation-free) --------------------
__device__ __nv_bfloat16 g_Xh[(size_t)NP * DIM], g_Xl[(size_t)NP * DIM];
__device__ __nv_bfloat16 g_Hh[(size_t)NP * DIM], g_Hl[(size_t)NP * DIM];
__device__ __nv_bfloat16 g_W1h[(size_t)NE * DIM * DIM], g_W1l[(size_t)NE * DIM * DIM];
__device__ __nv_bfloat16 g_W2h[(size_t)NE * DIM * DIM], g_W2l[(size_t)NE * DIM * DIM];
__device__ float g_Y[(size_t)NP * DIM];
__device__ int g_perm_src[NP];
__device__ int g_counts[NE], g_offsets[NE];

// ---------------- PTX helpers ------------------------------------------------
__device__ __forceinline__ uint32_t smem_u32(const void* p) {
    uint32_t a;
    asm("{ .reg .u64 t; cvta.to.shared.u64 t, %1; cvt.u32.u64 %0, t; }" : "=r"(a) : "l"(p));
    return a;
}
__device__ __forceinline__ void cpa16(uint32_t dst, const void* src) {
    asm volatile("cp.async.cg.shared.global [%0], [%1], 16;" :: "r"(dst), "l"(src));
}
#define CP_COMMIT() asm volatile("cp.async.commit_group;" ::: "memory")
#define CP_WAIT(n)  asm volatile("cp.async.wait_group %0;" :: "n"(n) : "memory")

__device__ __forceinline__ void ldsm4(uint32_t& r0, uint32_t& r1, uint32_t& r2,
                                      uint32_t& r3, uint32_t addr) {
    asm volatile("ldmatrix.sync.aligned.m8n8.x4.shared.b16 {%0,%1,%2,%3}, [%4];"
                 : "=r"(r0), "=r"(r1), "=r"(r2), "=r"(r3) : "r"(addr));
}
__device__ __forceinline__ void mma16816(float* c, const uint32_t* a,
                                         uint32_t b0, uint32_t b1) {
    asm volatile("mma.sync.aligned.m16n8k16.row.col.f32.bf16.bf16.f32 "
                 "{%0,%1,%2,%3}, {%4,%5,%6,%7}, {%8,%9}, {%0,%1,%2,%3};"
                 : "+f"(c[0]), "+f"(c[1]), "+f"(c[2]), "+f"(c[3])
                 : "r"(a[0]), "r"(a[1]), "r"(a[2]), "r"(a[3]), "r"(b0), "r"(b1));
}

// 16B-chunk XOR swizzle on 64B rows; conflict-free for 8-row ldmatrix groups.
__device__ __forceinline__ uint32_t sw_off(int r, int c16) {
    return (uint32_t)(r * 64 + ((c16 ^ ((r >> 1) & 3)) << 4));
}

// ---------------- fused grouping (single block) -------------------------------
__global__ void k_group(const int* __restrict__ idx) {
    __shared__ int sc[NE], scur[NE];
    const int tid = threadIdx.x;                 // 512 threads
    if (tid < NE) sc[tid] = 0;
    __syncthreads();

    int lc[NE];
    #pragma unroll
    for (int e = 0; e < NE; ++e) lc[e] = 0;
    for (int i = tid; i < NP; i += 512) lc[idx[i]]++;
    #pragma unroll
    for (int e = 0; e < NE; ++e)
        if (lc[e]) atomicAdd(&sc[e], lc[e]);
    __syncthreads();

    if (tid == 0) {
        int s = 0;
        for (int e = 0; e < NE; ++e) {
            g_counts[e]  = sc[e];
            g_offsets[e] = s;
            scur[e] = s;
            s += sc[e];
        }
    }
    __syncthreads();

    int base[NE];
    #pragma unroll
    for (int e = 0; e < NE; ++e)
        base[e] = lc[e] ? atomicAdd(&scur[e], lc[e]) : 0;

    int used[NE];
    #pragma unroll
    for (int e = 0; e < NE; ++e) used[e] = 0;
    for (int i = tid; i < NP; i += 512) {
        int e = idx[i];
        g_perm_src[base[e] + used[e]++] = i;
    }
}

// ---------------- fp32 -> bf16 hi/lo converts --------------------------------
union B8 { __nv_bfloat16 b[8]; uint4 u; };

__device__ __forceinline__ void split8(const float* v, B8& h, B8& l) {
    #pragma unroll
    for (int j = 0; j < 8; ++j) {
        __nv_bfloat16 hv = __float2bfloat16(v[j]);
        h.b[j] = hv;
        l.b[j] = __float2bfloat16(v[j] - __bfloat162float(hv));
    }
}

__global__ void k_convert_x(const float* __restrict__ x) {
    int i = blockIdx.x * blockDim.x + threadIdx.x;
    if (i >= NP * (DIM / 8)) return;
    int p  = i >> 7;
    int c8 = (i & 127) << 3;
    int tok = g_perm_src[p] >> 1;
    float v[8];
    *(float4*)&v[0] = *(const float4*)&x[(size_t)tok * DIM + c8];
    *(float4*)&v[4] = *(const float4*)&x[(size_t)tok * DIM + c8 + 4];
    B8 h, l; split8(v, h, l);
    *(uint4*)&g_Xh[(size_t)p * DIM + c8] = h.u;
    *(uint4*)&g_Xl[(size_t)p * DIM + c8] = l.u;
}

// Converts BOTH weight tensors in one launch.
__global__ void k_convert_w2(const float* __restrict__ W1,
                             const float* __restrict__ W2) {
    size_t i = (size_t)blockIdx.x * blockDim.x + threadIdx.x;
    const size_t half = (size_t)NE * DIM * DIM / 8;
    if (i >= 2 * half) return;
    const int which = (i >= half);
    const float* W = which ? W2 : W1;
    size_t b0 = (which ? (i - half) : i) * 8;
    float v[8];
    *(float4*)&v[0] = *(const float4*)&W[b0];
    *(float4*)&v[4] = *(const float4*)&W[b0 + 4];
    B8 h, l; split8(v, h, l);
    __nv_bfloat16* dh = which ? g_W2h : g_W1h;
    __nv_bfloat16* dl = which ? g_W2l : g_W1l;
    *(uint4*)&dh[b0] = h.u;
    *(uint4*)&dl[b0] = l.u;
}

// ---------------- mma.sync grouped GEMM (TM=128, TN=128, warp 64x32) ---------
// Fragment-level software pipeline: B fragments double-buffered across
// s-halves; A fragments streamed per mt with double buffer. No warp ever
// begins a phase waiting on an LDSM — loads always issued a step ahead,
// under MMA cover, including across half and chunk boundaries.
template <int STAGE>
__global__ __launch_bounds__(256, 2)
void k_gemm(const float* __restrict__ fw)
{
    extern __shared__ __align__(1024) char smem[];
    const int e   = blockIdx.z;
    const int cnt = g_counts[e];
    const int m0  = blockIdx.y * TM;
    if (m0 >= cnt) return;
    const int off = g_offsets[e];
    const int n0  = blockIdx.x * TN;
    const int tid = threadIdx.x;
    const int wid  = tid >> 5;
    const int lane = tid & 31;

    const uint32_t sb = smem_u32(smem);
    int* rowA = (int*)smem;
    if (tid < TM) rowA[tid] = off + min(m0 + tid, cnt - 1);
    __syncthreads();

    const __nv_bfloat16* __restrict__ Ah = (STAGE == 1) ? g_Xh : g_Hh;
    const __nv_bfloat16* __restrict__ Al = (STAGE == 1) ? g_Xl : g_Hl;
    const __nv_bfloat16* __restrict__ Bh =
        ((STAGE == 1) ? g_W1h : g_W2h) + (size_t)e * DIM * DIM;
    const __nv_bfloat16* __restrict__ Bl =
        ((STAGE == 1) ? g_W1l : g_W2l) + (size_t)e * DIM * DIM;

    const int r0l = tid >> 2, c0l = tid & 3;

    // ---- persistent load state: 4 advancing hi-pointers + lo deltas ----
    const __nv_bfloat16* pA0 = Ah + (size_t)rowA[r0l]      * DIM + c0l * 8;
    const __nv_bfloat16* pA1 = Ah + (size_t)rowA[r0l + 64] * DIM + c0l * 8;
    const __nv_bfloat16* pB0 = Bh + (size_t)(n0 + r0l)      * DIM + c0l * 8;
    const __nv_bfloat16* pB1 = Bh + (size_t)(n0 + r0l + 64) * DIM + c0l * 8;
    const ptrdiff_t dAl = Al - Ah;
    const ptrdiff_t dBl = Bl - Bh;
    const uint32_t st0 = sw_off(r0l,      c0l);
    const uint32_t st1 = sw_off(r0l + 64, c0l);

    auto load_to = [&](uint32_t base) {
        cpa16(base +          st0, pA0);
        cpa16(base +  8192u + st0, pA0 + dAl);
        cpa16(base + 16384u + st0, pB0);
        cpa16(base + 24576u + st0, pB0 + dBl);
        cpa16(base +          st1, pA1);
        cpa16(base +  8192u + st1, pA1 + dAl);
        cpa16(base + 16384u + st1, pB1);
        cpa16(base + 24576u + st1, pB1 + dBl);
        CP_COMMIT();
        pA0 += TK; pA1 += TK; pB0 += TK; pB1 += TK;
    };

    const int wm = wid & 1, wn = wid >> 1;
    const int lrow = lane & 15;
    const int lhi  = lane >> 4;

    uint32_t pA[4], pB[2];
    #pragma unroll
    for (int mt = 0; mt < 4; ++mt)
        pA[mt] = sw_off(wm * 64 + mt * 16 + lrow, lhi);            // AH region
    #pragma unroll
    for (int g = 0; g < 2; ++g)
        pB[g] = 16384u + sw_off(wn * 32 + g * 16 + lrow, lhi);     // BH region

    float acc[4][4][4];
    #pragma unroll
    for (int i = 0; i < 4; ++i)
        #pragma unroll
        for (int j = 0; j < 4; ++j)
            #pragma unroll
            for (int k = 0; k < 4; ++k) acc[i][j][k] = 0.0f;

    // fragment buffers
    uint32_t bhA[4][2], blA[4][2], bhB[4][2], blB[4][2];
    uint32_t ahb[2][4];

    // load both B-region fragment sets (regionAdd: 0 = BH, 8192 = BL)
    auto load_b = [&](uint32_t (&dst)[4][2], uint32_t stgX, uint32_t sxX,
                      uint32_t regionAdd) {
        #pragma unroll
        for (int g = 0; g < 2; ++g) {
            uint32_t t0, t1, t2, t3;
            ldsm4(t0, t1, t2, t3, stgX + regionAdd + (pB[g] ^ sxX));
            dst[g * 2 + 0][0] = t0; dst[g * 2 + 0][1] = t2;
            dst[g * 2 + 1][0] = t1; dst[g * 2 + 1][1] = t3;
        }
    };

    // one s-half: consumes (stgC,sxC) frags in bhC/blC/ahb[0], prefetches
    // next half's frags (stgN,sxN) into bhN/blN and ahb[0] (parity returns).
    auto half = [&](uint32_t stgC, uint32_t sxC, uint32_t stgN, uint32_t sxN,
                    uint32_t (&bhC)[4][2], uint32_t (&blC)[4][2],
                    uint32_t (&bhN)[4][2], uint32_t (&blN)[4][2]) {
        #pragma unroll
        for (int mt = 0; mt < 4; ++mt) {
            const int cur = mt & 1, nxt = cur ^ 1;
            uint32_t al[4];
            ldsm4(al[0], al[1], al[2], al[3],
                  stgC + 8192u + (pA[mt] ^ sxC));
            if (mt < 3)
                ldsm4(ahb[nxt][0], ahb[nxt][1], ahb[nxt][2], ahb[nxt][3],
                      stgC + (pA[mt + 1] ^ sxC));
            else
                ldsm4(ahb[nxt][0], ahb[nxt][1], ahb[nxt][2], ahb[nxt][3],
                      stgN + (pA[0] ^ sxN));
            // t1: ah x bh
            #pragma unroll
            for (int nt = 0; nt < 4; ++nt)
                mma16816(acc[mt][nt], ahb[cur], bhC[nt][0], bhC[nt][1]);
            if (mt == 2) load_b(bhN, stgN, sxN, 0u);
            // t2: al x bh
            #pragma unroll
            for (int nt = 0; nt < 4; ++nt)
                mma16816(acc[mt][nt], al, bhC[nt][0], bhC[nt][1]);
            if (mt == 3) load_b(blN, stgN, sxN, 8192u);
            // t3: ah x bl
            #pragma unroll
            for (int nt = 0; nt < 4; ++nt)
                mma16816(acc[mt][nt], ahb[cur], blC[nt][0], blC[nt][1]);
        }
    };

    const uint32_t stgLo = sb + SM_STG0;
    const uint32_t stgHi = sb + SM_STG0 + (NSTG - 1) * STG_BYTES;

    load_to(stgLo);
    load_to(stgLo + STG_BYTES);
    CP_WAIT(1);                    // stage 0 confirmed
    __syncthreads();

    // preload fragments for (chunk 0, s=0)
    load_b(bhA, stgLo, 0u, 0u);
    load_b(blA, stgLo, 0u, 8192u);
    ldsm4(ahb[0][0], ahb[0][1], ahb[0][2], ahb[0][3], stgLo + pA[0]);

    uint32_t stg  = stgLo;
    uint32_t lstg = stgLo + 2 * STG_BYTES;

    for (int c = 0; c < NCH; ++c) {
        if (c + 2 < NCH) {
            load_to(lstg);
            lstg = (lstg == stgHi) ? stgLo : (lstg + STG_BYTES);
        } else CP_COMMIT();
        const uint32_t stgn = (stg == stgHi) ? stgLo : (stg + STG_BYTES);

        half(stg, 0u, stg, 32u, bhA, blA, bhB, blB);       // s=0, prefetch s=1
        CP_WAIT(1);                 // confirms chunk c+1
        __syncthreads();
        half(stg, 32u, stgn, 0u, bhB, blB, bhA, blA);      // s=1, prefetch c+1
        __syncthreads();            // protect stage slot before next overwrite
        stg = stgn;
    }

    // ---------------- epilogue (coalesced stores; STAGE2 -> g_Y) -------------
    const int lq = lane >> 2;
    const int lr = lane & 3;
    #pragma unroll
    for (int mt = 0; mt < 4; ++mt) {
        #pragma unroll
        for (int half2 = 0; half2 < 2; ++half2) {
            const int m  = wm * 64 + mt * 16 + half2 * 8 + lq;
            const int gr = m0 + m;
            if (gr >= cnt) continue;
            const int p = off + gr;
            int   dstrow = p;
            float wt = 1.0f;
            if (STAGE == 2) {
                int src = g_perm_src[p];
                wt = fw[src];
                dstrow = src;
            }
            #pragma unroll
            for (int nt = 0; nt < 4; ++nt) {
                const int col = n0 + wn * 32 + nt * 8 + lr * 2;
                float v0 = fmaxf(acc[mt][nt][half2 * 2 + 0], 0.0f);
                float v1 = fmaxf(acc[mt][nt][half2 * 2 + 1], 0.0f);
                if (STAGE == 1) {
                    __nv_bfloat16 h0 = __float2bfloat16(v0);
                    __nv_bfloat16 h1 = __float2bfloat16(v1);
                    __nv_bfloat16 l0 = __float2bfloat16(v0 - __bfloat162float(h0));
                    __nv_bfloat16 l1 = __float2bfloat16(v1 - __bfloat162float(h1));
                    __nv_bfloat162 hp; hp.x = h0; hp.y = h1;
                    __nv_bfloat162 lp; lp.x = l0; lp.y = l1;
                    *(__nv_bfloat162*)&g_Hh[(size_t)p * DIM + col] = hp;
                    *(__nv_bfloat162*)&g_Hl[(size_t)p * DIM + col] = lp;
                } else {
                    float2 o; o.x = v0 * wt; o.y = v1 * wt;
                    *(float2*)&g_Y[(size_t)dstrow * DIM + col] = o;
                }
            }
        }
    }
}

// ---------------- combine: out[t] = Y[2t] + Y[2t+1] ---------------------------
__global__ void k_combine(float* __restrict__ out) {
    int i = blockIdx.x * blockDim.x + threadIdx.x;
    if (i >= T_TOK * DIM / 4) return;
    int t = i / (DIM / 4);
    const float4* y = (const float4*)g_Y;
    float4 a = y[(size_t)i + (size_t)t * (DIM / 4)];
    float4 b = y[(size_t)i + (size_t)t * (DIM / 4) + (DIM / 4)];
    float4 o; o.x = a.x + b.x; o.y = a.y + b.y; o.z = a.z + b.z; o.w = a.w + b.w;
    ((float4*)out)[i] = o;
}

// ---------------- launch ------------------------------------------------------
extern "C" void kernel_launch(void* const* d_in, const int* in_sizes, int n_in,
                              void* d_out, int out_size) {
    const float* x   = (const float*)d_in[0];
    const int*   fei = (const int*)d_in[1];
    const float* few = (const float*)d_in[2];
    const float* W1  = (const float*)d_in[3];
    const float* W2  = (const float*)d_in[4];
    float* out = (float*)d_out;

    cudaFuncSetAttribute(k_gemm<1>, cudaFuncAttributeMaxDynamicSharedMemorySize, SM_TOTAL);
    cudaFuncSetAttribute(k_gemm<2>, cudaFuncAttributeMaxDynamicSharedMemorySize, SM_TOTAL);

    dim3 grid(DIM / TN, MAXTILES, NE);   // 8 x 24 x 8 = 1536 CTAs

    k_group<<<1, 512>>>(fei);                                             // 1
    k_convert_x<<<(NP * (DIM / 8) + 255) / 256, 256>>>(x);                // 2
    k_convert_w2<<<(2 * NE * DIM * DIM / 8 + 255) / 256, 256>>>(W1, W2);  // 3
    k_gemm<1><<<grid, 256, SM_TOTAL>>>(few);                              // 4 <- ncu
    k_gemm<2><<<grid, 256, SM_TOTAL>>>(few);                              // 5
    k_combine<<<(T_TOK * DIM / 4 + 255) / 256, 256>>>(out);               // 6
}

// round 16
// speedup vs baseline: 1.1125x; 1.0002x over previous
#include <cuda_runtime.h>
#include <cuda_bf16.h>
#include <cstdint>

#define T_TOK 8192
#define DIM   1024
#define NE    8
#define NP    (T_TOK * 2)      // 16384 (token,expert) pairs

#define TM    128
#define TN    128
#define TK    32               // bf16 K per pipeline stage
#define NCH   (DIM / TK)       // 32 chunks
#define NSTG  3
#define MAXTILES 24

// stage layout: Ah(8K) Al(8K) Bh(8K) Bl(8K) = 32KB
#define STG_BYTES 32768u
#define SM_STG0 1024u
#define SM_TOTAL (1024 + NSTG * 32768)

// ---------------- static device scratch (allocation-free) --------------------
__device__ __nv_bfloat16 g_Xh[(size_t)NP * DIM], g_Xl[(size_t)NP * DIM];
__device__ __nv_bfloat16 g_Hh[(size_t)NP * DIM], g_Hl[(size_t)NP * DIM];
__device__ __nv_bfloat16 g_W1h[(size_t)NE * DIM * DIM], g_W1l[(size_t)NE * DIM * DIM];
__device__ __nv_bfloat16 g_W2h[(size_t)NE * DIM * DIM], g_W2l[(size_t)NE * DIM * DIM];
__device__ float g_Y[(size_t)NP * DIM];
__device__ int g_perm_src[NP];
__device__ int g_counts[NE], g_offsets[NE];

// ---------------- PTX helpers ------------------------------------------------
__device__ __forceinline__ uint32_t smem_u32(const void* p) {
    uint32_t a;
    asm("{ .reg .u64 t; cvta.to.shared.u64 t, %1; cvt.u32.u64 %0, t; }" : "=r"(a) : "l"(p));
    return a;
}
__device__ __forceinline__ void cpa16(uint32_t dst, const void* src) {
    asm volatile("cp.async.cg.shared.global [%0], [%1], 16;" :: "r"(dst), "l"(src));
}
#define CP_COMMIT() asm volatile("cp.async.commit_group;" ::: "memory")
#define CP_WAIT(n)  asm volatile("cp.async.wait_group %0;" :: "n"(n) : "memory")

__device__ __forceinline__ void ldsm4(uint32_t& r0, uint32_t& r1, uint32_t& r2,
                                      uint32_t& r3, uint32_t addr) {
    asm volatile("ldmatrix.sync.aligned.m8n8.x4.shared.b16 {%0,%1,%2,%3}, [%4];"
                 : "=r"(r0), "=r"(r1), "=r"(r2), "=r"(r3) : "r"(addr));
}
__device__ __forceinline__ void mma16816(float* c, const uint32_t* a,
                                         uint32_t b0, uint32_t b1) {
    asm volatile("mma.sync.aligned.m16n8k16.row.col.f32.bf16.bf16.f32 "
                 "{%0,%1,%2,%3}, {%4,%5,%6,%7}, {%8,%9}, {%0,%1,%2,%3};"
                 : "+f"(c[0]), "+f"(c[1]), "+f"(c[2]), "+f"(c[3])
                 : "r"(a[0]), "r"(a[1]), "r"(a[2]), "r"(a[3]), "r"(b0), "r"(b1));
}

// 16B-chunk XOR swizzle on 64B rows; conflict-free for 8-row ldmatrix groups.
__device__ __forceinline__ uint32_t sw_off(int r, int c16) {
    return (uint32_t)(r * 64 + ((c16 ^ ((r >> 1) & 3)) << 4));
}

// ---------------- fused grouping (single block) -------------------------------
__global__ void k_group(const int* __restrict__ idx) {
    __shared__ int sc[NE], scur[NE];
    const int tid = threadIdx.x;                 // 512 threads
    if (tid < NE) sc[tid] = 0;
    __syncthreads();

    int lc[NE];
    #pragma unroll
    for (int e = 0; e < NE; ++e) lc[e] = 0;
    for (int i = tid; i < NP; i += 512) lc[idx[i]]++;
    #pragma unroll
    for (int e = 0; e < NE; ++e)
        if (lc[e]) atomicAdd(&sc[e], lc[e]);
    __syncthreads();

    if (tid == 0) {
        int s = 0;
        for (int e = 0; e < NE; ++e) {
            g_counts[e]  = sc[e];
            g_offsets[e] = s;
            scur[e] = s;
            s += sc[e];
        }
    }
    __syncthreads();

    int base[NE];
    #pragma unroll
    for (int e = 0; e < NE; ++e)
        base[e] = lc[e] ? atomicAdd(&scur[e], lc[e]) : 0;

    int used[NE];
    #pragma unroll
    for (int e = 0; e < NE; ++e) used[e] = 0;
    for (int i = tid; i < NP; i += 512) {
        int e = idx[i];
        g_perm_src[base[e] + used[e]++] = i;
    }
}

// ---------------- fp32 -> bf16 hi/lo converts --------------------------------
union B8 { __nv_bfloat16 b[8]; uint4 u; };

__device__ __forceinline__ void split8(const float* v, B8& h, B8& l) {
    #pragma unroll
    for (int j = 0; j < 8; ++j) {
        __nv_bfloat16 hv = __float2bfloat16(v[j]);
        h.b[j] = hv;
        l.b[j] = __float2bfloat16(v[j] - __bfloat162float(hv));
    }
}

__global__ void k_convert_x(const float* __restrict__ x) {
    int i = blockIdx.x * blockDim.x + threadIdx.x;
    if (i >= NP * (DIM / 8)) return;
    int p  = i >> 7;
    int c8 = (i & 127) << 3;
    int tok = g_perm_src[p] >> 1;
    float v[8];
    *(float4*)&v[0] = *(const float4*)&x[(size_t)tok * DIM + c8];
    *(float4*)&v[4] = *(const float4*)&x[(size_t)tok * DIM + c8 + 4];
    B8 h, l; split8(v, h, l);
    *(uint4*)&g_Xh[(size_t)p * DIM + c8] = h.u;
    *(uint4*)&g_Xl[(size_t)p * DIM + c8] = l.u;
}

__global__ void k_convert_w(const float* __restrict__ W, int which) {
    size_t i = (size_t)blockIdx.x * blockDim.x + threadIdx.x;
    if (i >= (size_t)NE * DIM * DIM / 8) return;
    size_t b0 = i * 8;
    float v[8];
    *(float4*)&v[0] = *(const float4*)&W[b0];
    *(float4*)&v[4] = *(const float4*)&W[b0 + 4];
    B8 h, l; split8(v, h, l);
    __nv_bfloat16* dh = which ? g_W2h : g_W1h;
    __nv_bfloat16* dl = which ? g_W2l : g_W1l;
    *(uint4*)&dh[b0] = h.u;
    *(uint4*)&dl[b0] = l.u;
}

// ---------------- mma.sync grouped GEMM (TM=128, TN=128, warp 64x32) ---------
// Fragment-level software pipeline (r15 WIN) + single-barrier chunk loop:
//   half(s0) ; CP_WAIT(0) ; sync ; load_to(c+2) ; half(s1)
template <int STAGE>
__global__ __launch_bounds__(256, 2)
void k_gemm(const float* __restrict__ fw)
{
    extern __shared__ __align__(1024) char smem[];
    const int e   = blockIdx.z;
    const int cnt = g_counts[e];
    const int m0  = blockIdx.y * TM;
    if (m0 >= cnt) return;
    const int off = g_offsets[e];
    const int n0  = blockIdx.x * TN;
    const int tid = threadIdx.x;
    const int wid  = tid >> 5;
    const int lane = tid & 31;

    const uint32_t sb = smem_u32(smem);
    int* rowA = (int*)smem;
    if (tid < TM) rowA[tid] = off + min(m0 + tid, cnt - 1);
    __syncthreads();

    const __nv_bfloat16* __restrict__ Ah = (STAGE == 1) ? g_Xh : g_Hh;
    const __nv_bfloat16* __restrict__ Al = (STAGE == 1) ? g_Xl : g_Hl;
    const __nv_bfloat16* __restrict__ Bh =
        ((STAGE == 1) ? g_W1h : g_W2h) + (size_t)e * DIM * DIM;
    const __nv_bfloat16* __restrict__ Bl =
        ((STAGE == 1) ? g_W1l : g_W2l) + (size_t)e * DIM * DIM;

    const int r0l = tid >> 2, c0l = tid & 3;

    const __nv_bfloat16* pA0 = Ah + (size_t)rowA[r0l]      * DIM + c0l * 8;
    const __nv_bfloat16* pA1 = Ah + (size_t)rowA[r0l + 64] * DIM + c0l * 8;
    const __nv_bfloat16* pB0 = Bh + (size_t)(n0 + r0l)      * DIM + c0l * 8;
    const __nv_bfloat16* pB1 = Bh + (size_t)(n0 + r0l + 64) * DIM + c0l * 8;
    const ptrdiff_t dAl = Al - Ah;
    const ptrdiff_t dBl = Bl - Bh;
    const uint32_t st0 = sw_off(r0l,      c0l);
    const uint32_t st1 = sw_off(r0l + 64, c0l);

    auto load_to = [&](uint32_t base) {
        cpa16(base +          st0, pA0);
        cpa16(base +  8192u + st0, pA0 + dAl);
        cpa16(base + 16384u + st0, pB0);
        cpa16(base + 24576u + st0, pB0 + dBl);
        cpa16(base +          st1, pA1);
        cpa16(base +  8192u + st1, pA1 + dAl);
        cpa16(base + 16384u + st1, pB1);
        cpa16(base + 24576u + st1, pB1 + dBl);
        CP_COMMIT();
        pA0 += TK; pA1 += TK; pB0 += TK; pB1 += TK;
    };

    const int wm = wid & 1, wn = wid >> 1;
    const int lrow = lane & 15;
    const int lhi  = lane >> 4;

    uint32_t pA[4], pB[2];
    #pragma unroll
    for (int mt = 0; mt < 4; ++mt)
        pA[mt] = sw_off(wm * 64 + mt * 16 + lrow, lhi);            // AH region
    #pragma unroll
    for (int g = 0; g < 2; ++g)
        pB[g] = 16384u + sw_off(wn * 32 + g * 16 + lrow, lhi);     // BH region

    float acc[4][4][4];
    #pragma unroll
    for (int i = 0; i < 4; ++i)
        #pragma unroll
        for (int j = 0; j < 4; ++j)
            #pragma unroll
            for (int k = 0; k < 4; ++k) acc[i][j][k] = 0.0f;

    uint32_t bhA[4][2], blA[4][2], bhB[4][2], blB[4][2];
    uint32_t ahb[2][4];

    auto load_b = [&](uint32_t (&dst)[4][2], uint32_t stgX, uint32_t sxX,
                      uint32_t regionAdd) {
        #pragma unroll
        for (int g = 0; g < 2; ++g) {
            uint32_t t0, t1, t2, t3;
            ldsm4(t0, t1, t2, t3, stgX + regionAdd + (pB[g] ^ sxX));
            dst[g * 2 + 0][0] = t0; dst[g * 2 + 0][1] = t2;
            dst[g * 2 + 1][0] = t1; dst[g * 2 + 1][1] = t3;
        }
    };

    auto half = [&](uint32_t stgC, uint32_t sxC, uint32_t stgN, uint32_t sxN,
                    uint32_t (&bhC)[4][2], uint32_t (&blC)[4][2],
                    uint32_t (&bhN)[4][2], uint32_t (&blN)[4][2]) {
        #pragma unroll
        for (int mt = 0; mt < 4; ++mt) {
            const int cur = mt & 1, nxt = cur ^ 1;
            uint32_t al[4];
            ldsm4(al[0], al[1], al[2], al[3],
                  stgC + 8192u + (pA[mt] ^ sxC));
            if (mt < 3)
                ldsm4(ahb[nxt][0], ahb[nxt][1], ahb[nxt][2], ahb[nxt][3],
                      stgC + (pA[mt + 1] ^ sxC));
            else
                ldsm4(ahb[nxt][0], ahb[nxt][1], ahb[nxt][2], ahb[nxt][3],
                      stgN + (pA[0] ^ sxN));
            #pragma unroll
            for (int nt = 0; nt < 4; ++nt)
                mma16816(acc[mt][nt], ahb[cur], bhC[nt][0], bhC[nt][1]);
            if (mt == 2) load_b(bhN, stgN, sxN, 0u);
            #pragma unroll
            for (int nt = 0; nt < 4; ++nt)
                mma16816(acc[mt][nt], al, bhC[nt][0], bhC[nt][1]);
            if (mt == 3) load_b(blN, stgN, sxN, 8192u);
            #pragma unroll
            for (int nt = 0; nt < 4; ++nt)
                mma16816(acc[mt][nt], ahb[cur], blC[nt][0], blC[nt][1]);
        }
    };

    const uint32_t stgLo = sb + SM_STG0;
    const uint32_t stgHi = sb + SM_STG0 + (NSTG - 1) * STG_BYTES;

    load_to(stgLo);
    load_to(stgLo + STG_BYTES);
    CP_WAIT(1);                    // stage 0 confirmed
    __syncthreads();

    // preload fragments for (chunk 0, s=0)
    load_b(bhA, stgLo, 0u, 0u);
    load_b(blA, stgLo, 0u, 8192u);
    ldsm4(ahb[0][0], ahb[0][1], ahb[0][2], ahb[0][3], stgLo + pA[0]);

    uint32_t stg  = stgLo;
    uint32_t lstg = stgLo + 2 * STG_BYTES;

    for (int c = 0; c < NCH; ++c) {
        const uint32_t stgn = (stg == stgHi) ? stgLo : (stg + STG_BYTES);

        half(stg, 0u, stg, 32u, bhA, blA, bhB, blB);       // s=0, prefetch s=1
        CP_WAIT(0);                 // confirms stage c+1 (sole outstanding)
        __syncthreads();            // all warps done with stage c-1
        if (c + 2 < NCH) {
            load_to(lstg);          // overwrite stage c-1 slot
            lstg = (lstg == stgHi) ? stgLo : (lstg + STG_BYTES);
        }
        half(stg, 32u, stgn, 0u, bhB, blB, bhA, blA);      // s=1, prefetch c+1
        stg = stgn;
    }

    // ---------------- epilogue (coalesced stores; STAGE2 -> g_Y) -------------
    const int lq = lane >> 2;
    const int lr = lane & 3;
    #pragma unroll
    for (int mt = 0; mt < 4; ++mt) {
        #pragma unroll
        for (int half2 = 0; half2 < 2; ++half2) {
            const int m  = wm * 64 + mt * 16 + half2 * 8 + lq;
            const int gr = m0 + m;
            if (gr >= cnt) continue;
            const int p = off + gr;
            int   dstrow = p;
            float wt = 1.0f;
            if (STAGE == 2) {
                int src = g_perm_src[p];
                wt = fw[src];
                dstrow = src;
            }
            #pragma unroll
            for (int nt = 0; nt < 4; ++nt) {
                const int col = n0 + wn * 32 + nt * 8 + lr * 2;
                float v0 = fmaxf(acc[mt][nt][half2 * 2 + 0], 0.0f);
                float v1 = fmaxf(acc[mt][nt][half2 * 2 + 1], 0.0f);
                if (STAGE == 1) {
                    __nv_bfloat16 h0 = __float2bfloat16(v0);
                    __nv_bfloat16 h1 = __float2bfloat16(v1);
                    __nv_bfloat16 l0 = __float2bfloat16(v0 - __bfloat162float(h0));
                    __nv_bfloat16 l1 = __float2bfloat16(v1 - __bfloat162float(h1));
                    __nv_bfloat162 hp; hp.x = h0; hp.y = h1;
                    __nv_bfloat162 lp; lp.x = l0; lp.y = l1;
                    *(__nv_bfloat162*)&g_Hh[(size_t)p * DIM + col] = hp;
                    *(__nv_bfloat162*)&g_Hl[(size_t)p * DIM + col] = lp;
                } else {
                    float2 o; o.x = v0 * wt; o.y = v1 * wt;
                    *(float2*)&g_Y[(size_t)dstrow * DIM + col] = o;
                }
            }
        }
    }
}

// ---------------- combine: out[t] = Y[2t] + Y[2t+1] ---------------------------
__global__ void k_combine(float* __restrict__ out) {
    int i = blockIdx.x * blockDim.x + threadIdx.x;
    if (i >= T_TOK * DIM / 4) return;
    int t = i / (DIM / 4);
    const float4* y = (const float4*)g_Y;
    float4 a = y[(size_t)i + (size_t)t * (DIM / 4)];
    float4 b = y[(size_t)i + (size_t)t * (DIM / 4) + (DIM / 4)];
    float4 o; o.x = a.x + b.x; o.y = a.y + b.y; o.z = a.z + b.z; o.w = a.w + b.w;
    ((float4*)out)[i] = o;
}

// ---------------- launch ------------------------------------------------------
// Graph with stream forks: convert_W1 and convert_W2 run on side streams in
// parallel with (group -> convert_x); gemm1 joins on W1, gemm2 joins on W2.
// Streams/events created on first (non-captured) call; host objects only.
extern "C" void kernel_launch(void* const* d_in, const int* in_sizes, int n_in,
                              void* d_out, int out_size) {
    const float* x   = (const float*)d_in[0];
    const int*   fei = (const int*)d_in[1];
    const float* few = (const float*)d_in[2];
    const float* W1  = (const float*)d_in[3];
    const float* W2  = (const float*)d_in[4];
    float* out = (float*)d_out;

    static cudaStream_t sW1 = nullptr, sW2 = nullptr;
    static cudaEvent_t evRoot = nullptr, evW1 = nullptr, evW2 = nullptr;
    static bool inited = false;
    if (!inited) {
        cudaStreamCreateWithFlags(&sW1, cudaStreamNonBlocking);
        cudaStreamCreateWithFlags(&sW2, cudaStreamNonBlocking);
        cudaEventCreateWithFlags(&evRoot, cudaEventDisableTiming);
        cudaEventCreateWithFlags(&evW1, cudaEventDisableTiming);
        cudaEventCreateWithFlags(&evW2, cudaEventDisableTiming);
        cudaFuncSetAttribute(k_gemm<1>, cudaFuncAttributeMaxDynamicSharedMemorySize, SM_TOTAL);
        cudaFuncSetAttribute(k_gemm<2>, cudaFuncAttributeMaxDynamicSharedMemorySize, SM_TOTAL);
        inited = true;
    }

    dim3 grid(DIM / TN, MAXTILES, NE);   // 8 x 24 x 8 = 1536 CTAs
    const int nwcta = (NE * DIM * DIM / 8 + 255) / 256;

    // fork point
    cudaEventRecord(evRoot, 0);
    cudaStreamWaitEvent(sW1, evRoot, 0);
    cudaStreamWaitEvent(sW2, evRoot, 0);

    k_convert_w<<<nwcta, 256, 0, sW1>>>(W1, 0);
    cudaEventRecord(evW1, sW1);
    k_convert_w<<<nwcta, 256, 0, sW2>>>(W2, 1);
    cudaEventRecord(evW2, sW2);

    k_group<<<1, 512>>>(fei);
    k_convert_x<<<(NP * (DIM / 8) + 255) / 256, 256>>>(x);

    cudaStreamWaitEvent(0, evW1, 0);
    k_gemm<1><<<grid, 256, SM_TOTAL>>>(few);
    cudaStreamWaitEvent(0, evW2, 0);
    k_gemm<2><<<grid, 256, SM_TOTAL>>>(few);
    k_combine<<<(T_TOK * DIM / 4 + 255) / 256, 256>>>(out);
}